// round 16
// baseline (speedup 1.0000x reference)
#include <cuda_runtime.h>
#include <math.h>
#include <stdint.h>

// ---------------- problem constants ----------------
#define NB   512
#define NT   64
#define ND   512
#define NH   8
#define NDH  64
#define NFF  2048
#define NMOx 1040
#define SCALE_ETA 0.125f

// persistent kernel: 16 groups x 18 blocks of 256 threads (2 blocks/SM, different groups)
#define NGRP   16
#define GRPBLK 18
#define NBLK   (NGRP * GRPBLK)    // 288 blocks
#define NTHR   256                // 2 warpgroups per block
#define GWG    (GRPBLK * 2)       // 36 warpgroups per group
#define GROWS  (NB / NGRP)        // 32 batch rows per group

// cp.async staged smem: per stage A 32x36 + B 32x68 floats  (3-stage: proven)
#define STAGE_A_FLOATS (32 * 36)
#define STAGE_B_FLOATS (32 * 68)
#define STAGE_FLOATS   (STAGE_A_FLOATS + STAGE_B_FLOATS)   // 3328
#define NSTAGE 3
#define WG_SMEM_FLOATS (NSTAGE * STAGE_FLOATS)             // 9984
#define SMEM_BYTES (2 * WG_SMEM_FLOATS * 4)                // 79872 per block

// ---------------- device scratch ----------------
__device__ float  g_state[NB*NH*NDH*NDH];
__device__ float2 g_istats[NB*NT];
__device__ float2 g_lstats[NB];
__device__ float2 g_xstats[NB];
__device__ float  g_usnorm[NB*ND];
__device__ float  g_Q[(NB*NT + NB)*ND];
__device__ float  g_mctx[NB*ND];
__device__ float  g_y1a[NB*ND];
__device__ float  g_y1p[4*NB*ND];
__device__ float  g_y1ln[NB*ND];
__device__ float  g_moa[NB*NMOx];
__device__ float  g_mob[NB*NMOx];
__device__ float  g_ae[NB*16];
__device__ float  g_mod[NB*ND];
__device__ float  g_za[NB*NMOx];
__device__ float  g_zb[NB*NMOx];
__device__ float  g_wkvae[ND*NMOx];
__device__ float  g_x[NB*ND];
__device__ float  g_a1[NB*NFF];
__device__ float  g_wqr[ND*ND];
__device__ float  g_wor[ND*ND];
__device__ float  g_w1r[ND*NFF];
__device__ float  g_w2r[NFF*ND];
__device__ unsigned g_gcnt[NGRP*32];
__device__ unsigned g_ggen[NGRP*32];

__device__ __forceinline__ float tf32r(float x) {
    uint32_t u;
    asm("cvt.rna.tf32.f32 %0, %1;" : "=r"(u) : "f"(x));
    return __uint_as_float(u);
}

__device__ __forceinline__ float tanha(float x) {
    float r;
    asm("tanh.approx.f32 %0, %1;" : "=f"(r) : "f"(x));
    return r;
}

// ---------------- combined preamble kernel (stats + usnorm + wkvae) ----------------
#define PRE_STATS  33280
#define PRE_USN    33792
#define PRE_TOTAL  35872

__global__ void preamble_kernel(const float* __restrict__ item, const float* __restrict__ lastI,
                                const float* __restrict__ ustat,
                                const float* __restrict__ n1g, const float* __restrict__ n1b,
                                const float* __restrict__ Wk, const float* __restrict__ Wv,
                                const float* __restrict__ Wa, const float* __restrict__ We,
                                float2* __restrict__ istats, float2* __restrict__ lstats,
                                float* __restrict__ usnorm, float* __restrict__ wkvae) {
    int bid = blockIdx.x;
    if (bid >= PRE_USN) {
        int start = (bid - PRE_USN) * 128 + threadIdx.x;
        const int total = ND * NMOx;
        for (int idx = start; idx < total; idx += (PRE_TOTAL - PRE_USN) * 128) {
            int r = idx / NMOx, c = idx % NMOx;
            float v;
            if (c < 512)        v = Wk[r * 512 + c];
            else if (c < 1024)  v = Wv[r * 512 + (c - 512)];
            else if (c < 1032)  v = Wa[r * 8 + (c - 1024)];
            else                v = We[r * 8 + (c - 1032)];
            wkvae[idx] = v;
        }
        return;
    }
    const float* row;
    int r = bid;
    if (bid < NB * NT)        row = item + (size_t)r * ND;
    else if (bid < PRE_STATS) row = lastI + (size_t)(r - NB * NT) * ND;
    else                      row = ustat + (size_t)(r - PRE_STATS) * ND;
    float s = 0.f, ss = 0.f;
    for (int i = threadIdx.x; i < ND; i += blockDim.x) { float v = row[i]; s += v; ss = fmaf(v, v, ss); }
    for (int o = 16; o; o >>= 1) { s += __shfl_xor_sync(0xffffffffu, s, o); ss += __shfl_xor_sync(0xffffffffu, ss, o); }
    __shared__ float as[4], ass[4];
    __shared__ float smu, srs;
    int w = threadIdx.x >> 5, l = threadIdx.x & 31;
    if (l == 0) { as[w] = s; ass[w] = ss; }
    __syncthreads();
    if (threadIdx.x == 0) {
        s = as[0] + as[1] + as[2] + as[3];
        ss = ass[0] + ass[1] + ass[2] + ass[3];
        float mu = s / ND;
        float var = ss / ND - mu * mu;
        smu = mu; srs = rsqrtf(var + 1e-5f);
        if (bid < NB * NT)        istats[bid] = make_float2(mu, srs);
        else if (bid < PRE_STATS) lstats[bid - NB * NT] = make_float2(mu, srs);
    }
    if (bid >= PRE_STATS) {
        __syncthreads();
        float mu = smu, rs = srs;
        int rr = bid - PRE_STATS;
        for (int i = threadIdx.x; i < ND; i += blockDim.x)
            usnorm[(size_t)rr * ND + i] = (row[i] - mu) * rs * n1g[i] + n1b[i];
    }
}

// round the 4 standalone-GEMM weight matrices to tf32 (RNA) once (separate small launch)
__global__ void round_weights_kernel(const float* __restrict__ Wq, const float* __restrict__ Wo,
                                     const float* __restrict__ W1, const float* __restrict__ W2,
                                     float* __restrict__ wqr, float* __restrict__ wor,
                                     float* __restrict__ w1r, float* __restrict__ w2r) {
    const int N1 = ND * ND;
    const int N2 = 2 * N1;
    const int N3 = N2 + ND * NFF;
    const int N4 = N3 + NFF * ND;
    for (int i = blockIdx.x * blockDim.x + threadIdx.x; i < N4; i += gridDim.x * blockDim.x) {
        if (i < N1)       wqr[i] = tf32r(Wq[i]);
        else if (i < N2)  wor[i - N1] = tf32r(Wo[i - N1]);
        else if (i < N3)  w1r[i - N2] = tf32r(W1[i - N2]);
        else              w2r[i - N3] = tf32r(W2[i - N3]);
    }
}

__global__ void ln_stats_kernel(const float* __restrict__ x, float2* __restrict__ stats, int D) {
    int r = blockIdx.x;
    const float* row = x + (size_t)r * D;
    float s = 0.f, ss = 0.f;
    for (int i = threadIdx.x; i < D; i += blockDim.x) { float v = row[i]; s += v; ss = fmaf(v, v, ss); }
    for (int o = 16; o; o >>= 1) { s += __shfl_xor_sync(0xffffffffu, s, o); ss += __shfl_xor_sync(0xffffffffu, ss, o); }
    __shared__ float as[4], ass[4];
    int w = threadIdx.x >> 5, l = threadIdx.x & 31;
    if (l == 0) { as[w] = s; ass[w] = ss; }
    __syncthreads();
    if (threadIdx.x == 0) {
        s = as[0] + as[1] + as[2] + as[3];
        ss = ass[0] + ass[1] + ass[2] + ass[3];
        float mu = s / D;
        float var = ss / D - mu * mu;
        stats[r] = make_float2(mu, rsqrtf(var + 1e-5f));
    }
}

__global__ void l2n_kernel(float* __restrict__ x, int nseg) {
    int w = (blockIdx.x * blockDim.x + threadIdx.x) >> 5;
    int lane = threadIdx.x & 31;
    if (w >= nseg) return;
    float* seg = x + ((size_t)w << 6);
    float a = seg[lane], c = seg[lane + 32];
    float ss = a * a + c * c;
    for (int o = 16; o; o >>= 1) ss += __shfl_xor_sync(0xffffffffu, ss, o);
    float inv = 1.f / fmaxf(sqrtf(ss), 1e-12f);
    seg[lane] = a * inv;
    seg[lane + 32] = c * inv;
}

// ---------------- cp.async helpers ----------------
#define CP16(dstu, src) \
    asm volatile("cp.async.cg.shared.global [%0], [%1], 16;" :: "r"(dstu), "l"(src))
#define CP16P(dstu, src, sz) \
    asm volatile("cp.async.cg.shared.global [%0], [%1], 16, %2;" :: "r"(dstu), "l"(src), "r"(sz))
#define CP_COMMIT() asm volatile("cp.async.commit_group;" ::: "memory")
#define CP_WAIT1()  asm volatile("cp.async.wait_group 1;" ::: "memory")
#define CP_WAIT0()  asm volatile("cp.async.wait_group 0;" ::: "memory")

__device__ __forceinline__ void mma_tf32(float* c, const uint32_t* a, const uint32_t* b) {
    asm volatile(
        "mma.sync.aligned.m16n8k8.row.col.f32.tf32.tf32.f32 "
        "{%0,%1,%2,%3},{%4,%5,%6,%7},{%8,%9},{%0,%1,%2,%3};"
        : "+f"(c[0]), "+f"(c[1]), "+f"(c[2]), "+f"(c[3])
        : "r"(a[0]), "r"(a[1]), "r"(a[2]), "r"(a[3]), "r"(b[0]), "r"(b[1]));
}

// ---------------- pipelined standalone tf32 GEMM (R13 version, unchanged) ----------------
struct GemmP {
    const float*  A;   long lda;
    const float*  A2;
    const float*  Bm;  long ldb;
    float*        C;   long ldc;
    int M, N, K;
    int amode;                     // 0 raw, 1 LN, 2 LN+relu, 3 dual-source LN
    const float2* stats;
    const float2* stats2;
    const float*  lng; const float* lnb;
    const float*  bias;
    int epimode;                   // 0 none, 1 relu, 2 add addm
    const float*  addm; long ldadd;
};

__device__ __forceinline__ float gemm_a_elem(const GemmP& p, int r, int kk) {
    if (p.amode == 3) {
        float v; float2 s;
        if (r < NB * NT) { v = p.A[(size_t)r * p.lda + kk]; s = p.stats[r]; }
        else             { v = p.A2[(size_t)(r - NB * NT) * p.lda + kk]; s = p.stats2[r - NB * NT]; }
        return (v - s.x) * s.y * p.lng[kk] + p.lnb[kk];
    }
    float v = p.A[(size_t)r * p.lda + kk];
    if (p.amode) {
        float2 s = p.stats[r];
        v = (v - s.x) * s.y * p.lng[kk] + p.lnb[kk];
        if (p.amode == 2) v = fmaxf(v, 0.f);
    }
    return v;
}

#define SG_AS (64 * 36)
#define SG_BS (32 * 68)

__global__ void __launch_bounds__(128, 3) gemm_tf32_kernel(GemmP p) {
    __shared__ float sAs[2 * SG_AS];
    __shared__ float sBs[3 * SG_BS];
    uint32_t bsu = (uint32_t)__cvta_generic_to_shared(sBs);
    int tid = threadIdx.x;
    int warp = tid >> 5, lane = tid & 31;
    int g = lane >> 2, tig = lane & 3;
    int wm = (warp >> 1) * 32;
    int wn = (warp & 1) * 32;
    int row0 = blockIdx.y * 64;
    int n0 = blockIdx.x * 64;

    float acc[2][4][4];
#pragma unroll
    for (int mt = 0; mt < 2; mt++)
#pragma unroll
        for (int nt = 0; nt < 4; nt++)
#pragma unroll
            for (int e = 0; e < 4; e++) acc[mt][nt][e] = 0.f;

    int nkt = p.K >> 5;
    float ar[16];

#define SA_LDG(KT) do { \
    int _k0 = (KT) << 5; \
    _Pragma("unroll") \
    for (int j = 0; j < 4; j++) { \
        int c = tid + j * 128; \
        int rr = c >> 3, coff = (c & 7) << 2; \
        _Pragma("unroll") \
        for (int e = 0; e < 4; e++) \
            ar[j * 4 + e] = gemm_a_elem(p, row0 + rr, _k0 + coff + e); \
    } \
} while (0)

#define SA_STS(BUF) do { \
    _Pragma("unroll") \
    for (int j = 0; j < 4; j++) { \
        int c = tid + j * 128; \
        int rr = c >> 3, coff = (c & 7) << 2; \
        *(float4*)&(BUF)[rr * 36 + coff] = make_float4(tf32r(ar[j*4]), tf32r(ar[j*4+1]), \
                                                       tf32r(ar[j*4+2]), tf32r(ar[j*4+3])); \
    } \
} while (0)

#define SB_FILL(KT) do { \
    int _k0 = (KT) << 5; \
    uint32_t _st = bsu + (uint32_t)((KT) % 3) * SG_BS * 4u; \
    _Pragma("unroll") \
    for (int j = 0; j < 4; j++) { \
        int c = tid + j * 128; \
        int rr = c >> 4, coff = (c & 15) << 2; \
        int col = n0 + coff; \
        const float* src = p.Bm + (size_t)(_k0 + rr) * p.ldb + col; \
        int sz = (col < p.N) ? 16 : 0; \
        if (!sz) src = p.Bm; \
        CP16P(_st + (uint32_t)(rr * 68 + coff) * 4u, src, sz); \
    } \
    CP_COMMIT(); \
} while (0)

    SB_FILL(0);
    SB_FILL(1);
    SA_LDG(0); SA_STS(sAs);
    if (nkt > 1) SA_LDG(1);
    CP_WAIT1();
    __syncthreads();

    for (int kt = 0; kt < nkt; kt++) {
        float* As = sAs + (kt & 1) * SG_AS;
        float* Bs = sBs + (kt % 3) * SG_BS;
#pragma unroll
        for (int ks = 0; ks < 4; ks++) {
            int k8 = ks * 8;
            uint32_t a[2][4], b[4][2];
#pragma unroll
            for (int mt = 0; mt < 2; mt++) {
                int mb = wm + mt * 16 + g;
                a[mt][0] = __float_as_uint(As[mb * 36 + k8 + tig]);
                a[mt][1] = __float_as_uint(As[(mb + 8) * 36 + k8 + tig]);
                a[mt][2] = __float_as_uint(As[mb * 36 + k8 + tig + 4]);
                a[mt][3] = __float_as_uint(As[(mb + 8) * 36 + k8 + tig + 4]);
            }
#pragma unroll
            for (int nt = 0; nt < 4; nt++) {
                int nb = wn + nt * 8 + g;
                b[nt][0] = __float_as_uint(Bs[(k8 + tig) * 68 + nb]);
                b[nt][1] = __float_as_uint(Bs[(k8 + tig + 4) * 68 + nb]);
            }
#pragma unroll
            for (int mt = 0; mt < 2; mt++)
#pragma unroll
                for (int nt = 0; nt < 4; nt++)
                    mma_tf32(acc[mt][nt], a[mt], b[nt]);
        }
        if (kt + 1 < nkt) {
            SA_STS(sAs + ((kt + 1) & 1) * SG_AS);
            if (kt + 2 < nkt) {
                SA_LDG(kt + 2);
                SB_FILL(kt + 2);
                CP_WAIT1();
            } else {
                CP_WAIT0();
            }
        }
        __syncthreads();
    }
#undef SA_LDG
#undef SA_STS
#undef SB_FILL

#pragma unroll
    for (int mt = 0; mt < 2; mt++) {
#pragma unroll
        for (int nt = 0; nt < 4; nt++) {
#pragma unroll
            for (int e = 0; e < 4; e++) {
                int r = row0 + wm + mt * 16 + g + ((e >= 2) ? 8 : 0);
                int c = n0 + wn + nt * 8 + tig * 2 + (e & 1);
                if (c < p.N) {
                    float v = acc[mt][nt][e];
                    if (p.bias) v += p.bias[c];
                    if (p.epimode == 1) v = fmaxf(v, 0.f);
                    else if (p.epimode == 2) v += p.addm[(size_t)r * p.ldadd + c];
                    p.C[(size_t)r * p.ldc + c] = v;
                }
            }
        }
    }
}

// ---------------- persistent recurrence kernel (R13 structure + vectorized P4) ----------------

struct RecP {
    const float* item;
    const float2* istats;
    const float* usnorm;
    float* mctx;
    const float* Q;
    const float* init;
    float* y1a; float* y1p; float* y1ln;
    float* moa; float* mob; float* ae;
    float* modv;
    float* za; float* zb;
    float* state;
    const float* mcW1; const float* mcb1;
    const float* mcg; const float* mcbt;
    const float* mcW2; const float* mcb2;
    const float* wkvae;
    const float* ba; const float* be;
    const float* n1g; const float* n1b;
};

__device__ __forceinline__ void group_sync(int gi) {
    __syncthreads();
    if (threadIdx.x == 0) {
        volatile unsigned* cnt = &g_gcnt[gi * 32];
        volatile unsigned* gen = &g_ggen[gi * 32];
        unsigned g = *gen;
        __threadfence();
        if (atomicAdd((unsigned*)cnt, 1u) == GRPBLK - 1) {
            *cnt = 0;
            __threadfence();
            atomicAdd((unsigned*)gen, 1u);
        } else {
            while (*gen == g) { }
        }
        __threadfence();
    }
    __syncthreads();
}

__device__ __forceinline__ void wg_sync(int wg) {
    asm volatile("bar.sync %0, 128;" :: "r"(wg + 1) : "memory");
}

// fill one stage with cp.async: A 32x32 (row-major pad 36), B 32x64 (pad 68)
__device__ __forceinline__ void wg_fill(uint32_t stu, const float* __restrict__ A, long lda,
                                        const float* __restrict__ B, long ldb, int Ncols,
                                        int row0, int n0, int k0, int wgtid) {
#pragma unroll
    for (int i = 0; i < 2; i++) {
        int c = wgtid + i * 128;
        int row = c >> 3, coff = (c & 7) << 2;
        const float* src = A + (size_t)(row0 + row) * lda + k0 + coff;
        CP16(stu + (uint32_t)(row * 36 + coff) * 4u, src);
    }
#pragma unroll
    for (int i = 0; i < 4; i++) {
        int c = wgtid + i * 128;
        int row = c >> 4, coff = (c & 15) << 2;
        int col = n0 + coff;
        const float* src = B + (size_t)(k0 + row) * ldb + col;
        int sz = 16;
        if (col >= Ncols) { sz = 0; src = B; }
        CP16P(stu + (uint32_t)(STAGE_A_FLOATS + row * 68 + coff) * 4u, src, sz);
    }
    CP_COMMIT();
}

// pipelined warpgroup 32x64 tile GEMM, raw operands, K multiple of 32 (nkt >= 2)
__device__ void wg_gemm(int wg, int wgtid, uint32_t smu, float* smf,
                        const float* __restrict__ A, long lda,
                        const float* __restrict__ B, long ldb, int Ncols,
                        float* __restrict__ C, long ldc,
                        int row0, int n0, int K) {
    int warp = wgtid >> 5, lane = wgtid & 31;
    int gq = lane >> 2, tig = lane & 3;
    int wm = (warp >> 1) * 16;
    int wn = (warp & 1) * 32;
    float acc[4][4];
#pragma unroll
    for (int nt = 0; nt < 4; nt++)
#pragma unroll
        for (int e = 0; e < 4; e++) acc[nt][e] = 0.f;

    int nkt = K >> 5;
    wg_fill(smu, A, lda, B, ldb, Ncols, row0, n0, 0, wgtid);
    wg_fill(smu + STAGE_FLOATS * 4u, A, lda, B, ldb, Ncols, row0, n0, 32, wgtid);
    CP_WAIT1();
    wg_sync(wg);

    for (int kt = 0; kt < nkt; kt++) {
        int st = kt % NSTAGE;
        float* As = smf + st * STAGE_FLOATS;
        float* Bs = As + STAGE_A_FLOATS;
#pragma unroll
        for (int ks = 0; ks < 4; ks++) {
            int k8 = ks * 8;
            uint32_t a[4], b[4][2];
            int mb = wm + gq;
            a[0] = __float_as_uint(As[mb * 36 + k8 + tig]);
            a[1] = __float_as_uint(As[(mb + 8) * 36 + k8 + tig]);
            a[2] = __float_as_uint(As[mb * 36 + k8 + tig + 4]);
            a[3] = __float_as_uint(As[(mb + 8) * 36 + k8 + tig + 4]);
#pragma unroll
            for (int nt = 0; nt < 4; nt++) {
                int nb = wn + nt * 8 + gq;
                b[nt][0] = __float_as_uint(Bs[(k8 + tig) * 68 + nb]);
                b[nt][1] = __float_as_uint(Bs[(k8 + tig + 4) * 68 + nb]);
            }
#pragma unroll
            for (int nt = 0; nt < 4; nt++)
                mma_tf32(acc[nt], a, b[nt]);
        }
        if (kt + 1 < nkt) {
            if (kt + 2 < nkt) {
                wg_fill(smu + (uint32_t)((kt + 2) % NSTAGE) * STAGE_FLOATS * 4u,
                        A, lda, B, ldb, Ncols, row0, n0, (kt + 2) << 5, wgtid);
                CP_WAIT1();
            } else {
                CP_WAIT0();
            }
        }
        wg_sync(wg);
    }

#pragma unroll
    for (int nt = 0; nt < 4; nt++) {
#pragma unroll
        for (int e = 0; e < 4; e++) {
            int r = row0 + wm + gq + ((e >= 2) ? 8 : 0);
            int c = n0 + wn + nt * 8 + tig * 2 + (e & 1);
            if (c < Ncols)
                C[(size_t)r * ldc + c] = acc[nt][e];
        }
    }
}

// state init copy + initial read for one (b,h) pair (warpgroup)
__device__ void wg_read_pair(int wg, int wgtid, float* scratch, int bh, const RecP& P) {
    int b = bh >> 3, h = bh & 7;
    float* sq = scratch;
    if (wgtid < 64) sq[wgtid] = P.Q[((size_t)b * NT) * ND + h * 64 + wgtid];
    wg_sync(wg);
    int row = wgtid >> 1, half = wgtid & 1;
    const float* irow = P.init + ((size_t)bh << 12) + (row << 6) + half * 32;
    float* srow = P.state + ((size_t)bh << 12) + (row << 6) + half * 32;
    const float* qh = sq + half * 32;
    float4 s[8];
    float qdot = 0.f;
#pragma unroll
    for (int i = 0; i < 8; i++) {
        s[i] = *(const float4*)(irow + i * 4);
        *(float4*)(srow + i * 4) = s[i];
        qdot += s[i].x * qh[i*4] + s[i].y * qh[i*4+1] + s[i].z * qh[i*4+2] + s[i].w * qh[i*4+3];
    }
    qdot += __shfl_xor_sync(0xffffffffu, qdot, 1);
    if (half == 0) P.mctx[(size_t)b * ND + h * 64 + row] = qdot;
    wg_sync(wg);
}

// state update + fused next-context read (warpgroup)
__device__ void wg_update_pair(int wg, int wgtid, float* scratch, int bh, const RecP& P,
                               const float* __restrict__ qn, long qstride) {
    int b = bh >> 3, h = bh & 7;
    float* sk = scratch;
    float* sv = scratch + 64;
    float* sq = scratch + 128;
    float* sred = scratch + 192;
    const float* zra = P.za + (size_t)b * NMOx;
    const float* zrb = P.zb + (size_t)b * NMOx;
    if (wgtid < 64) {
        sk[wgtid] = zra[h * 64 + wgtid] + zrb[h * 64 + wgtid];
        sv[wgtid] = zra[512 + h * 64 + wgtid] + zrb[512 + h * 64 + wgtid];
        sq[wgtid] = qn[(size_t)b * qstride + h * 64 + wgtid];
    }
    wg_sync(wg);
    if (wgtid < 32) {
        float a = sk[wgtid], c = sk[wgtid + 32];
        float ss = a * a + c * c;
        for (int o = 16; o; o >>= 1) ss += __shfl_xor_sync(0xffffffffu, ss, o);
        if (wgtid == 0) sred[0] = fmaxf(sqrtf(ss), 1e-12f);
    }
    wg_sync(wg);
    float inv = 1.f / sred[0];
    const float* aerow = P.ae + (size_t)b * 16;
    float araw = (zra[1024 + h] + zrb[1024 + h]) + P.ba[h] + aerow[h];
    float eraw = (zra[1032 + h] + zrb[1032 + h]) + P.be[h] + aerow[8 + h];
    float alpha = 1.f / (1.f + expf(-araw));
    float eta = (1.f / (1.f + expf(-eraw))) * SCALE_ETA;
    float om = 1.f - alpha;

    int row = wgtid >> 1, half = wgtid & 1;
    float* srow = P.state + ((size_t)bh << 12) + (row << 6) + half * 32;
    float4 s[8];
#pragma unroll
    for (int i = 0; i < 8; i++) s[i] = *(float4*)(srow + i * 4);

    const float* kh = sk + half * 32;
    const float* qh = sq + half * 32;
    float pred = 0.f;
#pragma unroll
    for (int i = 0; i < 8; i++) {
        pred += s[i].x * kh[i*4] + s[i].y * kh[i*4+1] + s[i].z * kh[i*4+2] + s[i].w * kh[i*4+3];
    }
    pred += __shfl_xor_sync(0xffffffffu, pred, 1);
    pred *= inv;

    float coef = eta * (sv[row] - pred) * inv;
    float qdot = 0.f;
#pragma unroll
    for (int i = 0; i < 8; i++) {
        s[i].x = fmaf(coef, kh[i*4],   om * s[i].x);
        s[i].y = fmaf(coef, kh[i*4+1], om * s[i].y);
        s[i].z = fmaf(coef, kh[i*4+2], om * s[i].z);
        s[i].w = fmaf(coef, kh[i*4+3], om * s[i].w);
        *(float4*)(srow + i * 4) = s[i];
        qdot += s[i].x * qh[i*4] + s[i].y * qh[i*4+1] + s[i].z * qh[i*4+2] + s[i].w * qh[i*4+3];
    }
    qdot += __shfl_xor_sync(0xffffffffu, qdot, 1);
    if (half == 0) P.mctx[(size_t)b * ND + h * 64 + row] = qdot;
    wg_sync(wg);
}

__global__ void __launch_bounds__(NTHR, 2) recurrence_kernel(RecP P) {
    extern __shared__ float sm[];
    int tid = threadIdx.x;
    int wg = tid >> 7, wgtid = tid & 127;
    float* smf = sm + wg * WG_SMEM_FLOATS;
    uint32_t smu = (uint32_t)__cvta_generic_to_shared(smf);

    int gi = blockIdx.x % NGRP;
    int bg = blockIdx.x / NGRP;
    int wgig = bg * 2 + wg;
    int rbase = gi * GROWS;
    int pbase = rbase * NH;

    // pre-phase: y1a = usnorm @ mcW1_top (8 tiles, K=512)
    for (int it = wgig; it < 8; it += GWG)
        wg_gemm(wg, wgtid, smu, smf, P.usnorm, ND, P.mcW1, ND, ND,
                P.y1a, ND, rbase, it * 64, ND);
    // pre-phase: state init + initial read
    for (int p = wgig; p < GROWS * NH; p += GWG)
        wg_read_pair(wg, wgtid, smf, pbase + p, P);
    group_sync(gi);

    for (int t = 0; t < NT; t++) {
        // P1: y1b partials = mctx @ mcW1_bot, K-split 4 -> 32 tiles K=128
        for (int it = wgig; it < 32; it += GWG) {
            int kq = it >> 3, n0 = (it & 7) * 64;
            wg_gemm(wg, wgtid, smu, smf,
                    P.mctx + kq * 128, ND,
                    P.mcW1 + (size_t)(512 + kq * 128) * ND, ND, ND,
                    P.y1p + (size_t)kq * NB * ND, ND, rbase, n0, 128);
        }
        group_sync(gi);

        // P2: y1 = y1a + 4 partials + bias; LN+relu fused -> y1ln
        {
            int warpid = tid >> 5, lane = tid & 31;
            int widx = bg * 8 + warpid;
            if (widx < GROWS) {
                int r = rbase + widx;
                const float* pa = P.y1a + (size_t)r * ND;
                const float* p0 = P.y1p + (size_t)r * ND;
                const float* p1 = p0 + (size_t)NB * ND;
                const float* p2 = p1 + (size_t)NB * ND;
                const float* p3 = p2 + (size_t)NB * ND;
                float v[16];
                float s = 0.f, ss = 0.f;
#pragma unroll
                for (int j = 0; j < 16; j++) {
                    int c = lane + j * 32;
                    float vv = pa[c] + ((p0[c] + p1[c]) + (p2[c] + p3[c])) + P.mcb1[c];
                    v[j] = vv;
                    s += vv; ss = fmaf(vv, vv, ss);
                }
                for (int o = 16; o; o >>= 1) {
                    s += __shfl_xor_sync(0xffffffffu, s, o);
                    ss += __shfl_xor_sync(0xffffffffu, ss, o);
                }
                float mu = s / ND;
                float var = ss / ND - mu * mu;
                float rs = rsqrtf(var + 1e-5f);
                float* py = P.y1ln + (size_t)r * ND;
#pragma unroll
                for (int j = 0; j < 16; j++) {
                    int c = lane + j * 32;
                    float o = (v[j] - mu) * rs * P.mcg[c] + P.mcbt[c];
                    py[c] = fmaxf(o, 0.f);
                }
            }
        }
        group_sync(gi);

        // P3: mo partials = y1ln @ mcW2, K-split 2 -> 34 tiles K=256
        for (int it = wgig; it < 34; it += GWG) {
            int kh = it / 17, n0 = (it % 17) * 64;
            wg_gemm(wg, wgtid, smu, smf,
                    P.y1ln + kh * 256, ND,
                    P.mcW2 + (size_t)(kh * 256) * NMOx, NMOx, NMOx,
                    kh ? P.mob : P.moa, NMOx, rbase, n0, 256);
        }
        group_sync(gi);

        // P4: mo reduce + mod (vectorized float4, tanh.approx) ; ae columns
        {
            const float* item_t = P.item + (size_t)t * ND;
            const int ND4 = ND / 4;   // 128 float4 per row
            for (int i = bg * NTHR + tid; i < GROWS * ND4; i += GRPBLK * NTHR) {
                int b = rbase + (i >> 7);
                int d4 = (i & 127) << 2;
                const float* ma = P.moa + (size_t)b * NMOx;
                const float* mb = P.mob + (size_t)b * NMOx;
                float4 ga  = *(const float4*)(ma + d4);
                float4 gb  = *(const float4*)(mb + d4);
                float4 ba4 = *(const float4*)(ma + 512 + d4);
                float4 bb4 = *(const float4*)(mb + 512 + d4);
                float4 cg  = *(const float4*)(P.mcb2 + d4);
                float4 cb  = *(const float4*)(P.mcb2 + 512 + d4);
                float4 it4 = *(const float4*)(item_t + (size_t)b * NT * ND + d4);
                float4 g1  = *(const float4*)(P.n1g + d4);
                float4 b14 = *(const float4*)(P.n1b + d4);
                float2 st = P.istats[(size_t)b * NT + t];
                float4 o;
                {
                    float gm = ga.x + gb.x + cg.x;
                    float bt = ba4.x + bb4.x + cb.x;
                    float in = (it4.x - st.x) * st.y * g1.x + b14.x;
                    o.x = in * (1.f + tanha(gm)) + bt;
                }
                {
                    float gm = ga.y + gb.y + cg.y;
                    float bt = ba4.y + bb4.y + cb.y;
                    float in = (it4.y - st.x) * st.y * g1.y + b14.y;
                    o.y = in * (1.f + tanha(gm)) + bt;
                }
                {
                    float gm = ga.z + gb.z + cg.z;
                    float bt = ba4.z + bb4.z + cb.z;
                    float in = (it4.z - st.x) * st.y * g1.z + b14.z;
                    o.z = in * (1.f + tanha(gm)) + bt;
                }
                {
                    float gm = ga.w + gb.w + cg.w;
                    float bt = ba4.w + bb4.w + cb.w;
                    float in = (it4.w - st.x) * st.y * g1.w + b14.w;
                    o.w = in * (1.f + tanha(gm)) + bt;
                }
                *(float4*)(P.modv + (size_t)b * ND + d4) = o;
            }
            for (int i = bg * NTHR + tid; i < GROWS * 16; i += GRPBLK * NTHR) {
                int b = rbase + (i >> 4), c = i & 15;
                P.ae[(size_t)b * 16 + c] = P.moa[(size_t)b * NMOx + 1024 + c]
                                         + P.mob[(size_t)b * NMOx + 1024 + c]
                                         + P.mcb2[1024 + c];
            }
        }
        group_sync(gi);

        // P5: z partials = mod @ wkvae, K-split 2 -> 34 tiles K=256
        for (int it = wgig; it < 34; it += GWG) {
            int kh = it / 17, n0 = (it % 17) * 64;
            wg_gemm(wg, wgtid, smu, smf,
                    P.modv + kh * 256, ND,
                    P.wkvae + (size_t)(kh * 256) * NMOx, NMOx, NMOx,
                    kh ? P.zb : P.za, NMOx, rbase, n0, 256);
        }
        group_sync(gi);

        // P6: state update + fused next-context read
        {
            const float* qn; long qstride;
            if (t < NT - 1) { qn = P.Q + (size_t)(t + 1) * ND; qstride = (long)NT * ND; }
            else            { qn = P.Q + (size_t)NB * NT * ND; qstride = (long)ND; }
            for (int p = wgig; p < GROWS * NH; p += GWG)
                wg_update_pair(wg, wgtid, smf, pbase + p, P, qn, qstride);
        }
        group_sync(gi);
    }
}

// ---------------- host launcher ----------------

static void launch_gemm(const float* A, long lda, const float* Bm, long ldb, float* C, long ldc,
                        int M, int N, int K, int amode,
                        const float2* stats, const float* lng, const float* lnb,
                        const float* bias, int epi, const float* addm, long ldadd,
                        const float* A2 = nullptr, const float2* stats2 = nullptr) {
    GemmP p;
    p.A = A; p.lda = lda; p.A2 = A2; p.Bm = Bm; p.ldb = ldb; p.C = C; p.ldc = ldc;
    p.M = M; p.N = N; p.K = K; p.amode = amode;
    p.stats = stats; p.stats2 = stats2; p.lng = lng; p.lnb = lnb;
    p.bias = bias; p.epimode = epi; p.addm = addm; p.ldadd = ldadd;
    dim3 grid((N + 63) / 64, M / 64);
    gemm_tf32_kernel<<<grid, 128>>>(p);
}

extern "C" void kernel_launch(void* const* d_in, const int* in_sizes, int n_in,
                              void* d_out, int out_size) {
    const float* item  = (const float*)d_in[0];
    const float* ustat = (const float*)d_in[1];
    const float* lastI = (const float*)d_in[2];
    const float* init  = (const float*)d_in[3];
    const float* Wq    = (const float*)d_in[4];
    const float* Wk    = (const float*)d_in[5];
    const float* Wv    = (const float*)d_in[6];
    const float* Wa    = (const float*)d_in[7];
    const float* ba    = (const float*)d_in[8];
    const float* We    = (const float*)d_in[9];
    const float* be    = (const float*)d_in[10];
    const float* mcW1  = (const float*)d_in[11];
    const float* mcb1  = (const float*)d_in[12];
    const float* mcg   = (const float*)d_in[13];
    const float* mcbt  = (const float*)d_in[14];
    const float* mcW2  = (const float*)d_in[15];
    const float* mcb2  = (const float*)d_in[16];
    const float* Wo    = (const float*)d_in[17];
    const float* bo    = (const float*)d_in[18];
    const float* W1    = (const float*)d_in[19];
    const float* b1    = (const float*)d_in[20];
    const float* W2    = (const float*)d_in[21];
    const float* b2    = (const float*)d_in[22];
    const float* n1g   = (const float*)d_in[23];
    const float* n1b   = (const float*)d_in[24];
    const float* n2g   = (const float*)d_in[25];
    const float* n2b   = (const float*)d_in[26];
    float* out = (float*)d_out;

    float *state, *usnorm, *Q, *mctx, *y1a, *y1p, *y1ln, *moa, *mob, *ae, *modv, *za, *zb, *wkvae, *x, *a1;
    float *wqr, *wor, *w1r, *w2r;
    float2 *istats, *lstats, *xstats;
    cudaGetSymbolAddress((void**)&state,  g_state);
    cudaGetSymbolAddress((void**)&istats, g_istats);
    cudaGetSymbolAddress((void**)&lstats, g_lstats);
    cudaGetSymbolAddress((void**)&xstats, g_xstats);
    cudaGetSymbolAddress((void**)&usnorm, g_usnorm);
    cudaGetSymbolAddress((void**)&Q,      g_Q);
    cudaGetSymbolAddress((void**)&mctx,   g_mctx);
    cudaGetSymbolAddress((void**)&y1a,    g_y1a);
    cudaGetSymbolAddress((void**)&y1p,    g_y1p);
    cudaGetSymbolAddress((void**)&y1ln,   g_y1ln);
    cudaGetSymbolAddress((void**)&moa,    g_moa);
    cudaGetSymbolAddress((void**)&mob,    g_mob);
    cudaGetSymbolAddress((void**)&ae,     g_ae);
    cudaGetSymbolAddress((void**)&modv,   g_mod);
    cudaGetSymbolAddress((void**)&za,     g_za);
    cudaGetSymbolAddress((void**)&zb,     g_zb);
    cudaGetSymbolAddress((void**)&wkvae,  g_wkvae);
    cudaGetSymbolAddress((void**)&x,      g_x);
    cudaGetSymbolAddress((void**)&a1,     g_a1);
    cudaGetSymbolAddress((void**)&wqr,    g_wqr);
    cudaGetSymbolAddress((void**)&wor,    g_wor);
    cudaGetSymbolAddress((void**)&w1r,    g_w1r);
    cudaGetSymbolAddress((void**)&w2r,    g_w2r);

    cudaFuncSetAttribute(recurrence_kernel, cudaFuncAttributeMaxDynamicSharedMemorySize, SMEM_BYTES);

    // 1: combined preamble (stats + usnorm + wkvae)  — R13 launch structure
    preamble_kernel<<<PRE_TOTAL, 128>>>(item, lastI, ustat, n1g, n1b,
                                        Wk, Wv, Wa, We, istats, lstats, usnorm, wkvae);
    // 2: round standalone-GEMM weights to tf32 (RNA), separate small launch (overlaps)
    round_weights_kernel<<<2560, 256>>>(Wq, Wo, W1, W2, wqr, wor, w1r, w2r);
    // 3: Q (+qlast rows): LN(item|lastI) @ Wq_r
    launch_gemm(item, ND, wqr, ND, Q, ND, NB * NT + NB, ND, ND, 3,
                istats, n1g, n1b, nullptr, 0, nullptr, 0, lastI, lstats);
    // 4: l2-normalize per head
    l2n_kernel<<<((NB * NT + NB) * NH) / 8, 256>>>(Q, (NB * NT + NB) * NH);

    // 5: full recurrence — R13 config + vectorized P4
    RecP P;
    P.item = item; P.istats = istats; P.usnorm = usnorm; P.mctx = mctx;
    P.Q = Q; P.init = init;
    P.y1a = y1a; P.y1p = y1p; P.y1ln = y1ln;
    P.moa = moa; P.mob = mob; P.ae = ae; P.modv = modv;
    P.za = za; P.zb = zb; P.state = state;
    P.mcW1 = mcW1; P.mcb1 = mcb1; P.mcg = mcg; P.mcbt = mcbt;
    P.mcW2 = mcW2; P.mcb2 = mcb2; P.wkvae = wkvae;
    P.ba = ba; P.be = be; P.n1g = n1g; P.n1b = n1b;
    recurrence_kernel<<<NBLK, NTHR, SMEM_BYTES>>>(P);

    // readout + FFN (pipelined GEMMs on rounded weights)
    launch_gemm(mctx, ND, wor, ND, x, ND, NB, ND, ND, 0,
                nullptr, nullptr, nullptr, bo, 2, ustat, ND);
    ln_stats_kernel<<<NB, 128>>>(x, xstats, ND);
    launch_gemm(x, ND, w1r, NFF, a1, NFF, NB, NFF, ND, 1,
                xstats, n2g, n2b, b1, 1, nullptr, 0);
    launch_gemm(a1, NFF, w2r, ND, out, ND, NB, ND, NFF, 0,
                nullptr, nullptr, nullptr, b2, 2, x, ND);
}

// round 17
// speedup vs baseline: 1.0524x; 1.0524x over previous
#include <cuda_runtime.h>
#include <math.h>
#include <stdint.h>

// ---------------- problem constants ----------------
#define NB   512
#define NT   64
#define ND   512
#define NH   8
#define NDH  64
#define NFF  2048
#define NMOx 1040
#define SCALE_ETA 0.125f

// persistent kernel: 16 groups x 18 blocks of 256 threads (2 blocks/SM, different groups)
#define NGRP   16
#define GRPBLK 18
#define NBLK   (NGRP * GRPBLK)    // 288 blocks
#define NTHR   256                // 2 warpgroups per block
#define GWG    (GRPBLK * 2)       // 36 warpgroups per group
#define GROWS  (NB / NGRP)        // 32 batch rows per group

// cp.async staged smem: per stage A 32x36 + B 32x68 floats  (3-stage: proven)
#define STAGE_A_FLOATS (32 * 36)
#define STAGE_B_FLOATS (32 * 68)
#define STAGE_FLOATS   (STAGE_A_FLOATS + STAGE_B_FLOATS)   // 3328
#define NSTAGE 3
#define WG_SMEM_FLOATS (NSTAGE * STAGE_FLOATS)             // 9984
#define SMEM_BYTES (2 * WG_SMEM_FLOATS * 4)                // 79872 per block

// ---------------- device scratch ----------------
__device__ float  g_state[NB*NH*NDH*NDH];
__device__ float2 g_istats[NB*NT];
__device__ float2 g_lstats[NB];
__device__ float2 g_xstats[NB];
__device__ float  g_usnorm[NB*ND];
__device__ float  g_Q[(NB*NT + NB)*ND];
__device__ float  g_mctx[NB*ND];
__device__ float  g_y1a[NB*ND];
__device__ float  g_y1p[4*NB*ND];
__device__ float  g_y1ln[NB*ND];
__device__ float  g_moa[NB*NMOx];
__device__ float  g_mob[NB*NMOx];
__device__ float  g_ae[NB*16];
__device__ float  g_mod[NB*ND];
__device__ float  g_za[NB*NMOx];
__device__ float  g_zb[NB*NMOx];
__device__ float  g_wkvae[ND*NMOx];
__device__ float  g_x[NB*ND];
__device__ float  g_a1[NB*NFF];
// tf32-rounded copies of standalone-GEMM B weights (exact under cp.async truncation)
__device__ float  g_wqr[ND*ND];
__device__ float  g_wor[ND*ND];
__device__ float  g_w1r[ND*NFF];
__device__ float  g_w2r[NFF*ND];
__device__ unsigned g_gcnt[NGRP*32];
__device__ unsigned g_ggen[NGRP*32];

__device__ __forceinline__ float tf32r(float x) {
    uint32_t u;
    asm("cvt.rna.tf32.f32 %0, %1;" : "=r"(u) : "f"(x));
    return __uint_as_float(u);
}

// ---------------- combined preamble kernel (stats + usnorm + wkvae) ----------------
#define PRE_STATS  33280
#define PRE_USN    33792
#define PRE_TOTAL  35872

__global__ void preamble_kernel(const float* __restrict__ item, const float* __restrict__ lastI,
                                const float* __restrict__ ustat,
                                const float* __restrict__ n1g, const float* __restrict__ n1b,
                                const float* __restrict__ Wk, const float* __restrict__ Wv,
                                const float* __restrict__ Wa, const float* __restrict__ We,
                                float2* __restrict__ istats, float2* __restrict__ lstats,
                                float* __restrict__ usnorm, float* __restrict__ wkvae) {
    int bid = blockIdx.x;
    if (bid >= PRE_USN) {
        int start = (bid - PRE_USN) * 128 + threadIdx.x;
        const int total = ND * NMOx;
        for (int idx = start; idx < total; idx += (PRE_TOTAL - PRE_USN) * 128) {
            int r = idx / NMOx, c = idx % NMOx;
            float v;
            if (c < 512)        v = Wk[r * 512 + c];
            else if (c < 1024)  v = Wv[r * 512 + (c - 512)];
            else if (c < 1032)  v = Wa[r * 8 + (c - 1024)];
            else                v = We[r * 8 + (c - 1032)];
            wkvae[idx] = v;
        }
        return;
    }
    const float* row;
    int r = bid;
    if (bid < NB * NT)        row = item + (size_t)r * ND;
    else if (bid < PRE_STATS) row = lastI + (size_t)(r - NB * NT) * ND;
    else                      row = ustat + (size_t)(r - PRE_STATS) * ND;
    float s = 0.f, ss = 0.f;
    for (int i = threadIdx.x; i < ND; i += blockDim.x) { float v = row[i]; s += v; ss = fmaf(v, v, ss); }
    for (int o = 16; o; o >>= 1) { s += __shfl_xor_sync(0xffffffffu, s, o); ss += __shfl_xor_sync(0xffffffffu, ss, o); }
    __shared__ float as[4], ass[4];
    __shared__ float smu, srs;
    int w = threadIdx.x >> 5, l = threadIdx.x & 31;
    if (l == 0) { as[w] = s; ass[w] = ss; }
    __syncthreads();
    if (threadIdx.x == 0) {
        s = as[0] + as[1] + as[2] + as[3];
        ss = ass[0] + ass[1] + ass[2] + ass[3];
        float mu = s / ND;
        float var = ss / ND - mu * mu;
        smu = mu; srs = rsqrtf(var + 1e-5f);
        if (bid < NB * NT)        istats[bid] = make_float2(mu, srs);
        else if (bid < PRE_STATS) lstats[bid - NB * NT] = make_float2(mu, srs);
    }
    if (bid >= PRE_STATS) {
        __syncthreads();
        float mu = smu, rs = srs;
        int rr = bid - PRE_STATS;
        for (int i = threadIdx.x; i < ND; i += blockDim.x)
            usnorm[(size_t)rr * ND + i] = (row[i] - mu) * rs * n1g[i] + n1b[i];
    }
}

// round the 4 standalone-GEMM weight matrices to tf32 (RNA) once
__global__ void round_weights_kernel(const float* __restrict__ Wq, const float* __restrict__ Wo,
                                     const float* __restrict__ W1, const float* __restrict__ W2,
                                     float* __restrict__ wqr, float* __restrict__ wor,
                                     float* __restrict__ w1r, float* __restrict__ w2r) {
    const int N1 = ND * ND;
    const int N2 = 2 * N1;
    const int N3 = N2 + ND * NFF;
    const int N4 = N3 + NFF * ND;
    for (int i = blockIdx.x * blockDim.x + threadIdx.x; i < N4; i += gridDim.x * blockDim.x) {
        if (i < N1)       wqr[i] = tf32r(Wq[i]);
        else if (i < N2)  wor[i - N1] = tf32r(Wo[i - N1]);
        else if (i < N3)  w1r[i - N2] = tf32r(W1[i - N2]);
        else              w2r[i - N3] = tf32r(W2[i - N3]);
    }
}

__global__ void ln_stats_kernel(const float* __restrict__ x, float2* __restrict__ stats, int D) {
    int r = blockIdx.x;
    const float* row = x + (size_t)r * D;
    float s = 0.f, ss = 0.f;
    for (int i = threadIdx.x; i < D; i += blockDim.x) { float v = row[i]; s += v; ss = fmaf(v, v, ss); }
    for (int o = 16; o; o >>= 1) { s += __shfl_xor_sync(0xffffffffu, s, o); ss += __shfl_xor_sync(0xffffffffu, ss, o); }
    __shared__ float as[4], ass[4];
    int w = threadIdx.x >> 5, l = threadIdx.x & 31;
    if (l == 0) { as[w] = s; ass[w] = ss; }
    __syncthreads();
    if (threadIdx.x == 0) {
        s = as[0] + as[1] + as[2] + as[3];
        ss = ass[0] + ass[1] + ass[2] + ass[3];
        float mu = s / D;
        float var = ss / D - mu * mu;
        stats[r] = make_float2(mu, rsqrtf(var + 1e-5f));
    }
}

__global__ void l2n_kernel(float* __restrict__ x, int nseg) {
    int w = (blockIdx.x * blockDim.x + threadIdx.x) >> 5;
    int lane = threadIdx.x & 31;
    if (w >= nseg) return;
    float* seg = x + ((size_t)w << 6);
    float a = seg[lane], c = seg[lane + 32];
    float ss = a * a + c * c;
    for (int o = 16; o; o >>= 1) ss += __shfl_xor_sync(0xffffffffu, ss, o);
    float inv = 1.f / fmaxf(sqrtf(ss), 1e-12f);
    seg[lane] = a * inv;
    seg[lane + 32] = c * inv;
}

// ---------------- cp.async helpers ----------------
#define CP16(dstu, src) \
    asm volatile("cp.async.cg.shared.global [%0], [%1], 16;" :: "r"(dstu), "l"(src))
#define CP16P(dstu, src, sz) \
    asm volatile("cp.async.cg.shared.global [%0], [%1], 16, %2;" :: "r"(dstu), "l"(src), "r"(sz))
#define CP_COMMIT() asm volatile("cp.async.commit_group;" ::: "memory")
#define CP_WAIT1()  asm volatile("cp.async.wait_group 1;" ::: "memory")
#define CP_WAIT0()  asm volatile("cp.async.wait_group 0;" ::: "memory")

__device__ __forceinline__ void mma_tf32(float* c, const uint32_t* a, const uint32_t* b) {
    asm volatile(
        "mma.sync.aligned.m16n8k8.row.col.f32.tf32.tf32.f32 "
        "{%0,%1,%2,%3},{%4,%5,%6,%7},{%8,%9},{%0,%1,%2,%3};"
        : "+f"(c[0]), "+f"(c[1]), "+f"(c[2]), "+f"(c[3])
        : "r"(a[0]), "r"(a[1]), "r"(a[2]), "r"(a[3]), "r"(b[0]), "r"(b[1]));
}

// ---------------- pipelined standalone tf32 GEMM ----------------
struct GemmP {
    const float*  A;   long lda;
    const float*  A2;
    const float*  Bm;  long ldb;
    float*        C;   long ldc;
    int M, N, K;
    int amode;                     // 0 raw, 1 LN, 2 LN+relu, 3 dual-source LN
    const float2* stats;
    const float2* stats2;
    const float*  lng; const float* lnb;
    const float*  bias;
    int epimode;                   // 0 none, 1 relu, 2 add addm
    const float*  addm; long ldadd;
};

__device__ __forceinline__ float gemm_a_elem(const GemmP& p, int r, int kk) {
    if (p.amode == 3) {
        float v; float2 s;
        if (r < NB * NT) { v = p.A[(size_t)r * p.lda + kk]; s = p.stats[r]; }
        else             { v = p.A2[(size_t)(r - NB * NT) * p.lda + kk]; s = p.stats2[r - NB * NT]; }
        return (v - s.x) * s.y * p.lng[kk] + p.lnb[kk];
    }
    float v = p.A[(size_t)r * p.lda + kk];
    if (p.amode) {
        float2 s = p.stats[r];
        v = (v - s.x) * s.y * p.lng[kk] + p.lnb[kk];
        if (p.amode == 2) v = fmaxf(v, 0.f);
    }
    return v;
}

#define SG_AS (64 * 36)
#define SG_BS (32 * 68)

__global__ void __launch_bounds__(128, 3) gemm_tf32_kernel(GemmP p) {
    __shared__ float sAs[2 * SG_AS];
    __shared__ float sBs[3 * SG_BS];
    uint32_t bsu = (uint32_t)__cvta_generic_to_shared(sBs);
    int tid = threadIdx.x;
    int warp = tid >> 5, lane = tid & 31;
    int g = lane >> 2, tig = lane & 3;
    int wm = (warp >> 1) * 32;
    int wn = (warp & 1) * 32;
    int row0 = blockIdx.y * 64;
    int n0 = blockIdx.x * 64;

    float acc[2][4][4];
#pragma unroll
    for (int mt = 0; mt < 2; mt++)
#pragma unroll
        for (int nt = 0; nt < 4; nt++)
#pragma unroll
            for (int e = 0; e < 4; e++) acc[mt][nt][e] = 0.f;

    int nkt = p.K >> 5;
    float ar[16];

#define SA_LDG(KT) do { \
    int _k0 = (KT) << 5; \
    _Pragma("unroll") \
    for (int j = 0; j < 4; j++) { \
        int c = tid + j * 128; \
        int rr = c >> 3, coff = (c & 7) << 2; \
        _Pragma("unroll") \
        for (int e = 0; e < 4; e++) \
            ar[j * 4 + e] = gemm_a_elem(p, row0 + rr, _k0 + coff + e); \
    } \
} while (0)

#define SA_STS(BUF) do { \
    _Pragma("unroll") \
    for (int j = 0; j < 4; j++) { \
        int c = tid + j * 128; \
        int rr = c >> 3, coff = (c & 7) << 2; \
        *(float4*)&(BUF)[rr * 36 + coff] = make_float4(tf32r(ar[j*4]), tf32r(ar[j*4+1]), \
                                                       tf32r(ar[j*4+2]), tf32r(ar[j*4+3])); \
    } \
} while (0)

#define SB_FILL(KT) do { \
    int _k0 = (KT) << 5; \
    uint32_t _st = bsu + (uint32_t)((KT) % 3) * SG_BS * 4u; \
    _Pragma("unroll") \
    for (int j = 0; j < 4; j++) { \
        int c = tid + j * 128; \
        int rr = c >> 4, coff = (c & 15) << 2; \
        int col = n0 + coff; \
        const float* src = p.Bm + (size_t)(_k0 + rr) * p.ldb + col; \
        int sz = (col < p.N) ? 16 : 0; \
        if (!sz) src = p.Bm; \
        CP16P(_st + (uint32_t)(rr * 68 + coff) * 4u, src, sz); \
    } \
    CP_COMMIT(); \
} while (0)

    SB_FILL(0);
    SB_FILL(1);
    SA_LDG(0); SA_STS(sAs);
    if (nkt > 1) SA_LDG(1);
    CP_WAIT1();
    __syncthreads();

    for (int kt = 0; kt < nkt; kt++) {
        float* As = sAs + (kt & 1) * SG_AS;
        float* Bs = sBs + (kt % 3) * SG_BS;
#pragma unroll
        for (int ks = 0; ks < 4; ks++) {
            int k8 = ks * 8;
            uint32_t a[2][4], b[4][2];
#pragma unroll
            for (int mt = 0; mt < 2; mt++) {
                int mb = wm + mt * 16 + g;
                a[mt][0] = __float_as_uint(As[mb * 36 + k8 + tig]);
                a[mt][1] = __float_as_uint(As[(mb + 8) * 36 + k8 + tig]);
                a[mt][2] = __float_as_uint(As[mb * 36 + k8 + tig + 4]);
                a[mt][3] = __float_as_uint(As[(mb + 8) * 36 + k8 + tig + 4]);
            }
#pragma unroll
            for (int nt = 0; nt < 4; nt++) {
                int nb = wn + nt * 8 + g;
                b[nt][0] = __float_as_uint(Bs[(k8 + tig) * 68 + nb]);
                b[nt][1] = __float_as_uint(Bs[(k8 + tig + 4) * 68 + nb]);
            }
#pragma unroll
            for (int mt = 0; mt < 2; mt++)
#pragma unroll
                for (int nt = 0; nt < 4; nt++)
                    mma_tf32(acc[mt][nt], a[mt], b[nt]);
        }
        if (kt + 1 < nkt) {
            SA_STS(sAs + ((kt + 1) & 1) * SG_AS);
            if (kt + 2 < nkt) {
                SA_LDG(kt + 2);
                SB_FILL(kt + 2);
                CP_WAIT1();
            } else {
                CP_WAIT0();
            }
        }
        __syncthreads();
    }
#undef SA_LDG
#undef SA_STS
#undef SB_FILL

#pragma unroll
    for (int mt = 0; mt < 2; mt++) {
#pragma unroll
        for (int nt = 0; nt < 4; nt++) {
#pragma unroll
            for (int e = 0; e < 4; e++) {
                int r = row0 + wm + mt * 16 + g + ((e >= 2) ? 8 : 0);
                int c = n0 + wn + nt * 8 + tig * 2 + (e & 1);
                if (c < p.N) {
                    float v = acc[mt][nt][e];
                    if (p.bias) v += p.bias[c];
                    if (p.epimode == 1) v = fmaxf(v, 0.f);
                    else if (p.epimode == 2) v += p.addm[(size_t)r * p.ldadd + c];
                    p.C[(size_t)r * p.ldc + c] = v;
                }
            }
        }
    }
}

// ---------------- persistent recurrence kernel (R13 exact) ----------------

struct RecP {
    const float* item;
    const float2* istats;
    const float* usnorm;
    float* mctx;
    const float* Q;
    const float* init;
    float* y1a; float* y1p; float* y1ln;
    float* moa; float* mob; float* ae;
    float* modv;
    float* za; float* zb;
    float* state;
    const float* mcW1; const float* mcb1;
    const float* mcg; const float* mcbt;
    const float* mcW2; const float* mcb2;
    const float* wkvae;
    const float* ba; const float* be;
    const float* n1g; const float* n1b;
};

__device__ __forceinline__ void group_sync(int gi) {
    __syncthreads();
    if (threadIdx.x == 0) {
        volatile unsigned* cnt = &g_gcnt[gi * 32];
        volatile unsigned* gen = &g_ggen[gi * 32];
        unsigned g = *gen;
        __threadfence();
        if (atomicAdd((unsigned*)cnt, 1u) == GRPBLK - 1) {
            *cnt = 0;
            __threadfence();
            atomicAdd((unsigned*)gen, 1u);
        } else {
            while (*gen == g) { }
        }
        __threadfence();
    }
    __syncthreads();
}

__device__ __forceinline__ void wg_sync(int wg) {
    asm volatile("bar.sync %0, 128;" :: "r"(wg + 1) : "memory");
}

// fill one stage with cp.async: A 32x32 (row-major pad 36), B 32x64 (pad 68)
__device__ __forceinline__ void wg_fill(uint32_t stu, const float* __restrict__ A, long lda,
                                        const float* __restrict__ B, long ldb, int Ncols,
                                        int row0, int n0, int k0, int wgtid) {
#pragma unroll
    for (int i = 0; i < 2; i++) {
        int c = wgtid + i * 128;
        int row = c >> 3, coff = (c & 7) << 2;
        const float* src = A + (size_t)(row0 + row) * lda + k0 + coff;
        CP16(stu + (uint32_t)(row * 36 + coff) * 4u, src);
    }
#pragma unroll
    for (int i = 0; i < 4; i++) {
        int c = wgtid + i * 128;
        int row = c >> 4, coff = (c & 15) << 2;
        int col = n0 + coff;
        const float* src = B + (size_t)(k0 + row) * ldb + col;
        int sz = 16;
        if (col >= Ncols) { sz = 0; src = B; }
        CP16P(stu + (uint32_t)(STAGE_A_FLOATS + row * 68 + coff) * 4u, src, sz);
    }
    CP_COMMIT();
}

// pipelined warpgroup 32x64 tile GEMM, raw operands, K multiple of 32 (nkt >= 2)
__device__ void wg_gemm(int wg, int wgtid, uint32_t smu, float* smf,
                        const float* __restrict__ A, long lda,
                        const float* __restrict__ B, long ldb, int Ncols,
                        float* __restrict__ C, long ldc,
                        int row0, int n0, int K) {
    int warp = wgtid >> 5, lane = wgtid & 31;
    int gq = lane >> 2, tig = lane & 3;
    int wm = (warp >> 1) * 16;
    int wn = (warp & 1) * 32;
    float acc[4][4];
#pragma unroll
    for (int nt = 0; nt < 4; nt++)
#pragma unroll
        for (int e = 0; e < 4; e++) acc[nt][e] = 0.f;

    int nkt = K >> 5;
    wg_fill(smu, A, lda, B, ldb, Ncols, row0, n0, 0, wgtid);
    wg_fill(smu + STAGE_FLOATS * 4u, A, lda, B, ldb, Ncols, row0, n0, 32, wgtid);
    CP_WAIT1();
    wg_sync(wg);

    for (int kt = 0; kt < nkt; kt++) {
        int st = kt % NSTAGE;
        float* As = smf + st * STAGE_FLOATS;
        float* Bs = As + STAGE_A_FLOATS;
#pragma unroll
        for (int ks = 0; ks < 4; ks++) {
            int k8 = ks * 8;
            uint32_t a[4], b[4][2];
            int mb = wm + gq;
            a[0] = __float_as_uint(As[mb * 36 + k8 + tig]);
            a[1] = __float_as_uint(As[(mb + 8) * 36 + k8 + tig]);
            a[2] = __float_as_uint(As[mb * 36 + k8 + tig + 4]);
            a[3] = __float_as_uint(As[(mb + 8) * 36 + k8 + tig + 4]);
#pragma unroll
            for (int nt = 0; nt < 4; nt++) {
                int nb = wn + nt * 8 + gq;
                b[nt][0] = __float_as_uint(Bs[(k8 + tig) * 68 + nb]);
                b[nt][1] = __float_as_uint(Bs[(k8 + tig + 4) * 68 + nb]);
            }
#pragma unroll
            for (int nt = 0; nt < 4; nt++)
                mma_tf32(acc[nt], a, b[nt]);
        }
        if (kt + 1 < nkt) {
            if (kt + 2 < nkt) {
                wg_fill(smu + (uint32_t)((kt + 2) % NSTAGE) * STAGE_FLOATS * 4u,
                        A, lda, B, ldb, Ncols, row0, n0, (kt + 2) << 5, wgtid);
                CP_WAIT1();
            } else {
                CP_WAIT0();
            }
        }
        wg_sync(wg);
    }

#pragma unroll
    for (int nt = 0; nt < 4; nt++) {
#pragma unroll
        for (int e = 0; e < 4; e++) {
            int r = row0 + wm + gq + ((e >= 2) ? 8 : 0);
            int c = n0 + wn + nt * 8 + tig * 2 + (e & 1);
            if (c < Ncols)
                C[(size_t)r * ldc + c] = acc[nt][e];
        }
    }
}

// state init copy + initial read for one (b,h) pair (warpgroup)
__device__ void wg_read_pair(int wg, int wgtid, float* scratch, int bh, const RecP& P) {
    int b = bh >> 3, h = bh & 7;
    float* sq = scratch;
    if (wgtid < 64) sq[wgtid] = P.Q[((size_t)b * NT) * ND + h * 64 + wgtid];
    wg_sync(wg);
    int row = wgtid >> 1, half = wgtid & 1;
    const float* irow = P.init + ((size_t)bh << 12) + (row << 6) + half * 32;
    float* srow = P.state + ((size_t)bh << 12) + (row << 6) + half * 32;
    const float* qh = sq + half * 32;
    float4 s[8];
    float qdot = 0.f;
#pragma unroll
    for (int i = 0; i < 8; i++) {
        s[i] = *(const float4*)(irow + i * 4);
        *(float4*)(srow + i * 4) = s[i];
        qdot += s[i].x * qh[i*4] + s[i].y * qh[i*4+1] + s[i].z * qh[i*4+2] + s[i].w * qh[i*4+3];
    }
    qdot += __shfl_xor_sync(0xffffffffu, qdot, 1);
    if (half == 0) P.mctx[(size_t)b * ND + h * 64 + row] = qdot;
    wg_sync(wg);
}

// state update + fused next-context read (warpgroup)
__device__ void wg_update_pair(int wg, int wgtid, float* scratch, int bh, const RecP& P,
                               const float* __restrict__ qn, long qstride) {
    int b = bh >> 3, h = bh & 7;
    float* sk = scratch;
    float* sv = scratch + 64;
    float* sq = scratch + 128;
    float* sred = scratch + 192;
    const float* zra = P.za + (size_t)b * NMOx;
    const float* zrb = P.zb + (size_t)b * NMOx;
    if (wgtid < 64) {
        sk[wgtid] = zra[h * 64 + wgtid] + zrb[h * 64 + wgtid];
        sv[wgtid] = zra[512 + h * 64 + wgtid] + zrb[512 + h * 64 + wgtid];
        sq[wgtid] = qn[(size_t)b * qstride + h * 64 + wgtid];
    }
    wg_sync(wg);
    if (wgtid < 32) {
        float a = sk[wgtid], c = sk[wgtid + 32];
        float ss = a * a + c * c;
        for (int o = 16; o; o >>= 1) ss += __shfl_xor_sync(0xffffffffu, ss, o);
        if (wgtid == 0) sred[0] = fmaxf(sqrtf(ss), 1e-12f);
    }
    wg_sync(wg);
    float inv = 1.f / sred[0];
    const float* aerow = P.ae + (size_t)b * 16;
    float araw = (zra[1024 + h] + zrb[1024 + h]) + P.ba[h] + aerow[h];
    float eraw = (zra[1032 + h] + zrb[1032 + h]) + P.be[h] + aerow[8 + h];
    float alpha = 1.f / (1.f + expf(-araw));
    float eta = (1.f / (1.f + expf(-eraw))) * SCALE_ETA;
    float om = 1.f - alpha;

    int row = wgtid >> 1, half = wgtid & 1;
    float* srow = P.state + ((size_t)bh << 12) + (row << 6) + half * 32;
    float4 s[8];
#pragma unroll
    for (int i = 0; i < 8; i++) s[i] = *(float4*)(srow + i * 4);

    const float* kh = sk + half * 32;
    const float* qh = sq + half * 32;
    float pred = 0.f;
#pragma unroll
    for (int i = 0; i < 8; i++) {
        pred += s[i].x * kh[i*4] + s[i].y * kh[i*4+1] + s[i].z * kh[i*4+2] + s[i].w * kh[i*4+3];
    }
    pred += __shfl_xor_sync(0xffffffffu, pred, 1);
    pred *= inv;

    float coef = eta * (sv[row] - pred) * inv;
    float qdot = 0.f;
#pragma unroll
    for (int i = 0; i < 8; i++) {
        s[i].x = fmaf(coef, kh[i*4],   om * s[i].x);
        s[i].y = fmaf(coef, kh[i*4+1], om * s[i].y);
        s[i].z = fmaf(coef, kh[i*4+2], om * s[i].z);
        s[i].w = fmaf(coef, kh[i*4+3], om * s[i].w);
        *(float4*)(srow + i * 4) = s[i];
        qdot += s[i].x * qh[i*4] + s[i].y * qh[i*4+1] + s[i].z * qh[i*4+2] + s[i].w * qh[i*4+3];
    }
    qdot += __shfl_xor_sync(0xffffffffu, qdot, 1);
    if (half == 0) P.mctx[(size_t)b * ND + h * 64 + row] = qdot;
    wg_sync(wg);
}

__global__ void __launch_bounds__(NTHR, 2) recurrence_kernel(RecP P) {
    extern __shared__ float sm[];
    int tid = threadIdx.x;
    int wg = tid >> 7, wgtid = tid & 127;
    float* smf = sm + wg * WG_SMEM_FLOATS;
    uint32_t smu = (uint32_t)__cvta_generic_to_shared(smf);

    int gi = blockIdx.x % NGRP;
    int bg = blockIdx.x / NGRP;
    int wgig = bg * 2 + wg;
    int rbase = gi * GROWS;
    int pbase = rbase * NH;

    // pre-phase: y1a = usnorm @ mcW1_top (8 tiles, K=512)
    for (int it = wgig; it < 8; it += GWG)
        wg_gemm(wg, wgtid, smu, smf, P.usnorm, ND, P.mcW1, ND, ND,
                P.y1a, ND, rbase, it * 64, ND);
    // pre-phase: state init + initial read
    for (int p = wgig; p < GROWS * NH; p += GWG)
        wg_read_pair(wg, wgtid, smf, pbase + p, P);
    group_sync(gi);

    for (int t = 0; t < NT; t++) {
        // P1: y1b partials = mctx @ mcW1_bot, K-split 4 -> 32 tiles K=128
        for (int it = wgig; it < 32; it += GWG) {
            int kq = it >> 3, n0 = (it & 7) * 64;
            wg_gemm(wg, wgtid, smu, smf,
                    P.mctx + kq * 128, ND,
                    P.mcW1 + (size_t)(512 + kq * 128) * ND, ND, ND,
                    P.y1p + (size_t)kq * NB * ND, ND, rbase, n0, 128);
        }
        group_sync(gi);

        // P2: y1 = y1a + 4 partials + bias; LN+relu fused -> y1ln
        {
            int warpid = tid >> 5, lane = tid & 31;
            int widx = bg * 8 + warpid;
            if (widx < GROWS) {
                int r = rbase + widx;
                const float* pa = P.y1a + (size_t)r * ND;
                const float* p0 = P.y1p + (size_t)r * ND;
                const float* p1 = p0 + (size_t)NB * ND;
                const float* p2 = p1 + (size_t)NB * ND;
                const float* p3 = p2 + (size_t)NB * ND;
                float v[16];
                float s = 0.f, ss = 0.f;
#pragma unroll
                for (int j = 0; j < 16; j++) {
                    int c = lane + j * 32;
                    float vv = pa[c] + ((p0[c] + p1[c]) + (p2[c] + p3[c])) + P.mcb1[c];
                    v[j] = vv;
                    s += vv; ss = fmaf(vv, vv, ss);
                }
                for (int o = 16; o; o >>= 1) {
                    s += __shfl_xor_sync(0xffffffffu, s, o);
                    ss += __shfl_xor_sync(0xffffffffu, ss, o);
                }
                float mu = s / ND;
                float var = ss / ND - mu * mu;
                float rs = rsqrtf(var + 1e-5f);
                float* py = P.y1ln + (size_t)r * ND;
#pragma unroll
                for (int j = 0; j < 16; j++) {
                    int c = lane + j * 32;
                    float o = (v[j] - mu) * rs * P.mcg[c] + P.mcbt[c];
                    py[c] = fmaxf(o, 0.f);
                }
            }
        }
        group_sync(gi);

        // P3: mo partials = y1ln @ mcW2, K-split 2 -> 34 tiles K=256
        for (int it = wgig; it < 34; it += GWG) {
            int kh = it / 17, n0 = (it % 17) * 64;
            wg_gemm(wg, wgtid, smu, smf,
                    P.y1ln + kh * 256, ND,
                    P.mcW2 + (size_t)(kh * 256) * NMOx, NMOx, NMOx,
                    kh ? P.mob : P.moa, NMOx, rbase, n0, 256);
        }
        group_sync(gi);

        // P4: mo reduce + mod = i_norm*(1+tanh(gamma))+beta ; ae columns
        {
            const float* item_t = P.item + (size_t)t * ND;
            for (int i = bg * NTHR + tid; i < GROWS * ND; i += GRPBLK * NTHR) {
                int b = rbase + (i >> 9), d = i & 511;
                const float* ma = P.moa + (size_t)b * NMOx;
                const float* mb = P.mob + (size_t)b * NMOx;
                float gm = ma[d] + mb[d] + P.mcb2[d];
                float bt = ma[512 + d] + mb[512 + d] + P.mcb2[512 + d];
                float2 st = P.istats[(size_t)b * NT + t];
                float inorm = (item_t[(size_t)b * NT * ND + d] - st.x) * st.y * P.n1g[d] + P.n1b[d];
                P.modv[(size_t)b * ND + d] = inorm * (1.f + tanhf(gm)) + bt;
            }
            for (int i = bg * NTHR + tid; i < GROWS * 16; i += GRPBLK * NTHR) {
                int b = rbase + (i >> 4), c = i & 15;
                P.ae[(size_t)b * 16 + c] = P.moa[(size_t)b * NMOx + 1024 + c]
                                         + P.mob[(size_t)b * NMOx + 1024 + c]
                                         + P.mcb2[1024 + c];
            }
        }
        group_sync(gi);

        // P5: z partials = mod @ wkvae, K-split 2 -> 34 tiles K=256
        for (int it = wgig; it < 34; it += GWG) {
            int kh = it / 17, n0 = (it % 17) * 64;
            wg_gemm(wg, wgtid, smu, smf,
                    P.modv + kh * 256, ND,
                    P.wkvae + (size_t)(kh * 256) * NMOx, NMOx, NMOx,
                    kh ? P.zb : P.za, NMOx, rbase, n0, 256);
        }
        group_sync(gi);

        // P6: state update + fused next-context read
        {
            const float* qn; long qstride;
            if (t < NT - 1) { qn = P.Q + (size_t)(t + 1) * ND; qstride = (long)NT * ND; }
            else            { qn = P.Q + (size_t)NB * NT * ND; qstride = (long)ND; }
            for (int p = wgig; p < GROWS * NH; p += GWG)
                wg_update_pair(wg, wgtid, smf, pbase + p, P, qn, qstride);
        }
        group_sync(gi);
    }
}

// ---------------- host launcher ----------------

static void launch_gemm(const float* A, long lda, const float* Bm, long ldb, float* C, long ldc,
                        int M, int N, int K, int amode,
                        const float2* stats, const float* lng, const float* lnb,
                        const float* bias, int epi, const float* addm, long ldadd,
                        const float* A2 = nullptr, const float2* stats2 = nullptr) {
    GemmP p;
    p.A = A; p.lda = lda; p.A2 = A2; p.Bm = Bm; p.ldb = ldb; p.C = C; p.ldc = ldc;
    p.M = M; p.N = N; p.K = K; p.amode = amode;
    p.stats = stats; p.stats2 = stats2; p.lng = lng; p.lnb = lnb;
    p.bias = bias; p.epimode = epi; p.addm = addm; p.ldadd = ldadd;
    dim3 grid((N + 63) / 64, M / 64);
    gemm_tf32_kernel<<<grid, 128>>>(p);
}

extern "C" void kernel_launch(void* const* d_in, const int* in_sizes, int n_in,
                              void* d_out, int out_size) {
    const float* item  = (const float*)d_in[0];
    const float* ustat = (const float*)d_in[1];
    const float* lastI = (const float*)d_in[2];
    const float* init  = (const float*)d_in[3];
    const float* Wq    = (const float*)d_in[4];
    const float* Wk    = (const float*)d_in[5];
    const float* Wv    = (const float*)d_in[6];
    const float* Wa    = (const float*)d_in[7];
    const float* ba    = (const float*)d_in[8];
    const float* We    = (const float*)d_in[9];
    const float* be    = (const float*)d_in[10];
    const float* mcW1  = (const float*)d_in[11];
    const float* mcb1  = (const float*)d_in[12];
    const float* mcg   = (const float*)d_in[13];
    const float* mcbt  = (const float*)d_in[14];
    const float* mcW2  = (const float*)d_in[15];
    const float* mcb2  = (const float*)d_in[16];
    const float* Wo    = (const float*)d_in[17];
    const float* bo    = (const float*)d_in[18];
    const float* W1    = (const float*)d_in[19];
    const float* b1    = (const float*)d_in[20];
    const float* W2    = (const float*)d_in[21];
    const float* b2    = (const float*)d_in[22];
    const float* n1g   = (const float*)d_in[23];
    const float* n1b   = (const float*)d_in[24];
    const float* n2g   = (const float*)d_in[25];
    const float* n2b   = (const float*)d_in[26];
    float* out = (float*)d_out;

    float *state, *usnorm, *Q, *mctx, *y1a, *y1p, *y1ln, *moa, *mob, *ae, *modv, *za, *zb, *wkvae, *x, *a1;
    float *wqr, *wor, *w1r, *w2r;
    float2 *istats, *lstats, *xstats;
    cudaGetSymbolAddress((void**)&state,  g_state);
    cudaGetSymbolAddress((void**)&istats, g_istats);
    cudaGetSymbolAddress((void**)&lstats, g_lstats);
    cudaGetSymbolAddress((void**)&xstats, g_xstats);
    cudaGetSymbolAddress((void**)&usnorm, g_usnorm);
    cudaGetSymbolAddress((void**)&Q,      g_Q);
    cudaGetSymbolAddress((void**)&mctx,   g_mctx);
    cudaGetSymbolAddress((void**)&y1a,    g_y1a);
    cudaGetSymbolAddress((void**)&y1p,    g_y1p);
    cudaGetSymbolAddress((void**)&y1ln,   g_y1ln);
    cudaGetSymbolAddress((void**)&moa,    g_moa);
    cudaGetSymbolAddress((void**)&mob,    g_mob);
    cudaGetSymbolAddress((void**)&ae,     g_ae);
    cudaGetSymbolAddress((void**)&modv,   g_mod);
    cudaGetSymbolAddress((void**)&za,     g_za);
    cudaGetSymbolAddress((void**)&zb,     g_zb);
    cudaGetSymbolAddress((void**)&wkvae,  g_wkvae);
    cudaGetSymbolAddress((void**)&x,      g_x);
    cudaGetSymbolAddress((void**)&a1,     g_a1);
    cudaGetSymbolAddress((void**)&wqr,    g_wqr);
    cudaGetSymbolAddress((void**)&wor,    g_wor);
    cudaGetSymbolAddress((void**)&w1r,    g_w1r);
    cudaGetSymbolAddress((void**)&w2r,    g_w2r);

    cudaFuncSetAttribute(recurrence_kernel, cudaFuncAttributeMaxDynamicSharedMemorySize, SMEM_BYTES);

    // 1: combined preamble (stats + usnorm + wkvae)
    preamble_kernel<<<PRE_TOTAL, 128>>>(item, lastI, ustat, n1g, n1b,
                                        Wk, Wv, Wa, We, istats, lstats, usnorm, wkvae);
    // 2: round the standalone-GEMM B weights to tf32 (RNA)
    round_weights_kernel<<<2560, 256>>>(Wq, Wo, W1, W2, wqr, wor, w1r, w2r);
    // 3: Q (+qlast rows): LN(item|lastI) @ Wq_r
    launch_gemm(item, ND, wqr, ND, Q, ND, NB * NT + NB, ND, ND, 3,
                istats, n1g, n1b, nullptr, 0, nullptr, 0, lastI, lstats);
    // 4: l2-normalize per head
    l2n_kernel<<<((NB * NT + NB) * NH) / 8, 256>>>(Q, (NB * NT + NB) * NH);

    // 5: full recurrence — 2 blocks/SM (different groups), 3-stage pipeline
    RecP P;
    P.item = item; P.istats = istats; P.usnorm = usnorm; P.mctx = mctx;
    P.Q = Q; P.init = init;
    P.y1a = y1a; P.y1p = y1p; P.y1ln = y1ln;
    P.moa = moa; P.mob = mob; P.ae = ae; P.modv = modv;
    P.za = za; P.zb = zb; P.state = state;
    P.mcW1 = mcW1; P.mcb1 = mcb1; P.mcg = mcg; P.mcbt = mcbt;
    P.mcW2 = mcW2; P.mcb2 = mcb2; P.wkvae = wkvae;
    P.ba = ba; P.be = be; P.n1g = n1g; P.n1b = n1b;
    recurrence_kernel<<<NBLK, NTHR, SMEM_BYTES>>>(P);

    // readout + FFN (pipelined GEMMs on rounded weights)
    launch_gemm(mctx, ND, wor, ND, x, ND, NB, ND, ND, 0,
                nullptr, nullptr, nullptr, bo, 2, ustat, ND);
    ln_stats_kernel<<<NB, 128>>>(x, xstats, ND);
    launch_gemm(x, ND, w1r, NFF, a1, NFF, NB, NFF, ND, 1,
                xstats, n2g, n2b, b1, 1, nullptr, 0);
    launch_gemm(a1, NFF, w2r, ND, out, ND, NB, ND, NFF, 0,
                nullptr, nullptr, nullptr, b2, 2, x, ND);
}